// round 1
// baseline (speedup 1.0000x reference)
#include <cuda_runtime.h>
#include <cstddef>

// ---------------- problem constants ----------------
#define Jn    24
#define Cc    32      // channels per joint (in == out)
#define KT    15
#define PADn  7
#define Bn    32
#define Tn    4096
#define GP    12      // pooled pairs = J/2
#define TT    128     // t tile per block
#define XROWS 128     // 4 joint slots * 32 ch
#define XPITCH 142    // TT + 14
#define NEG   0.2f

#define WS_PER_K (2 * 96 * 32)          // [j][ci][r] per tap
#define SMEM_BYTES (XROWS * XPITCH * 4 + WS_PER_K * 4)   // 72704 + 24576 = 97280

// Repacked weights: [g][k][j][ci][r], zeros baked in for missing neighbors.
__device__ float g_wpack[GP * KT * WS_PER_K];            // 4.4 MB

// ---------------- f32x2 helpers ----------------
__device__ __forceinline__ unsigned long long pack2(float a, float b) {
    unsigned long long r;
    asm("mov.b64 %0, {%1, %2};" : "=l"(r) : "f"(a), "f"(b));
    return r;
}
__device__ __forceinline__ void unpack2(unsigned long long v, float& a, float& b) {
    asm("mov.b64 {%0, %1}, %2;" : "=f"(a), "=f"(b) : "l"(v));
}
__device__ __forceinline__ unsigned long long fma2(unsigned long long a,
                                                   unsigned long long b,
                                                   unsigned long long c) {
    unsigned long long d;
    asm("fma.rn.f32x2 %0, %1, %2, %3;" : "=l"(d) : "l"(a), "l"(b), "l"(c));
    return d;
}

// ---------------- weight repack (coalesced staging layout) ----------------
__global__ void repack_weights_kernel(const float* __restrict__ w) {
    int idx = blockIdx.x * blockDim.x + threadIdx.x;
    const int total = GP * KT * WS_PER_K;
    if (idx >= total) return;
    int r   = idx & 31;
    int ci  = (idx >> 5) % 96;
    int rest = idx / (96 * 32);
    int j = rest & 1;      // rest = (g*KT + k)*2 + j
    rest >>= 1;
    int k = rest % KT;
    int g = rest / KT;
    int oj = 2 * g + j;                       // output joint
    int injoint = oj - 1 + (ci >> 5);         // neighbor joint for this ci slot
    float v = 0.f;
    if (injoint >= 0 && injoint < Jn) {
        int oc = oj * Cc + r;
        int ic = injoint * Cc + (ci & 31);
        v = w[((size_t)oc * (Jn * Cc) + ic) * KT + k];
    }
    g_wpack[idx] = v;
}

// ---------------- main fused kernel ----------------
__global__ void __launch_bounds__(256, 2)
skel_main_kernel(const float* __restrict__ x,
                 const float* __restrict__ bias,
                 float* __restrict__ out) {
    extern __shared__ float smem[];
    float* Xs = smem;                       // [128][142]
    float* Ws = smem + XROWS * XPITCH;      // [2][96][32]

    const int t0 = blockIdx.x * TT;
    const int g  = blockIdx.y;
    const int b  = blockIdx.z;

    const int tid   = threadIdx.x;
    const int lane  = tid & 31;
    const int wgrp  = tid >> 5;             // 0..7
    const int jj    = wgrp >> 2;            // joint within pair (0/1)
    const int rbase = (wgrp & 3) * 8;       // 8 out-channels per thread

    // ---- stage X: joints 2g-1 .. 2g+2, t in [t0-7, t0+135)
    {
        const int jbase = 2 * g - 1;
        for (int idx = tid; idx < XROWS * XPITCH; idx += 256) {
            int c = idx / XPITCH;
            int u = idx - c * XPITCH;
            int jq = jbase + (c >> 5);
            int tg = t0 - PADn + u;
            float v = 0.f;
            if (jq >= 0 && jq < Jn && tg >= 0 && tg < Tn)
                v = x[((size_t)b * (Jn * Cc) + jq * Cc + (c & 31)) * Tn + tg];
            Xs[idx] = v;
        }
    }

    unsigned long long acc[8][2];
#pragma unroll
    for (int r = 0; r < 8; r++) { acc[r][0] = 0ull; acc[r][1] = 0ull; }

    const float* wpk_base = g_wpack + (size_t)g * KT * WS_PER_K;

    for (int k = 0; k < KT; k++) {
        __syncthreads();
        // stage Ws[j][ci][r] for this tap (coalesced from repacked layout)
        const float* src = wpk_base + (size_t)k * WS_PER_K;
#pragma unroll
        for (int i = 0; i < WS_PER_K / 256; i++)
            Ws[i * 256 + tid] = src[i * 256 + tid];
        __syncthreads();

        const float* xrow0 = Xs + (jj * 32) * XPITCH + (lane + k);
        const float* wcol0 = Ws + jj * (96 * 32) + rbase;
#pragma unroll 4
        for (int ci = 0; ci < 96; ci++) {
            const float* xr = xrow0 + ci * XPITCH;
            unsigned long long p0 = pack2(xr[0],  xr[32]);
            unsigned long long p1 = pack2(xr[64], xr[96]);
            const float* wc = wcol0 + ci * 32;
#pragma unroll
            for (int r = 0; r < 8; r++) {
                float wv = wc[r];                       // broadcast LDS
                unsigned long long wp = pack2(wv, wv);
                acc[r][0] = fma2(wp, p0, acc[r][0]);
                acc[r][1] = fma2(wp, p1, acc[r][1]);
            }
        }
    }

    // ---- epilogue: bias, pool pair, LeakyReLU
    float yv[8][4];
#pragma unroll
    for (int r = 0; r < 8; r++) {
        float bv = bias[(2 * g + jj) * Cc + rbase + r];
        unpack2(acc[r][0], yv[r][0], yv[r][1]);
        unpack2(acc[r][1], yv[r][2], yv[r][3]);
#pragma unroll
        for (int i = 0; i < 4; i++) yv[r][i] += bv;
    }

    __syncthreads();                 // all reads of Xs/Ws done; reuse smem
    float* buf = smem;               // [32 slots][128 threads] conflict-free
    if (jj == 1) {
        int btid = tid - 128;
#pragma unroll
        for (int r = 0; r < 8; r++)
#pragma unroll
            for (int i = 0; i < 4; i++)
                buf[(r * 4 + i) * 128 + btid] = yv[r][i];
    }
    __syncthreads();
    if (jj == 0) {
#pragma unroll
        for (int r = 0; r < 8; r++) {
            int oc = g * Cc + rbase + r;
            float* orow = out + ((size_t)b * (GP * Cc) + oc) * Tn + t0 + lane;
#pragma unroll
            for (int i = 0; i < 4; i++) {
                float m = 0.5f * (yv[r][i] + buf[(r * 4 + i) * 128 + tid]);
                m = (m >= 0.f) ? m : NEG * m;
                orow[32 * i] = m;
            }
        }
    }
}

// ---------------- launch ----------------
extern "C" void kernel_launch(void* const* d_in, const int* in_sizes, int n_in,
                              void* d_out, int out_size) {
    const float* x    = (const float*)d_in[0];
    const float* w    = (const float*)d_in[1];
    const float* bias = (const float*)d_in[2];
    // d_in[3] = mask (static block-tridiagonal topology, applied structurally)
    // d_in[4] = pool_pairs (static consecutive pairs)
    float* out = (float*)d_out;

    cudaFuncSetAttribute(skel_main_kernel,
                         cudaFuncAttributeMaxDynamicSharedMemorySize, SMEM_BYTES);

    const int total_w = GP * KT * WS_PER_K;
    repack_weights_kernel<<<(total_w + 255) / 256, 256>>>(w);

    dim3 grid(Tn / TT, GP, Bn);
    skel_main_kernel<<<grid, 256, SMEM_BYTES>>>(x, bias, out);
}